// round 10
// baseline (speedup 1.0000x reference)
#include <cuda_runtime.h>
#include <cuda_bf16.h>
#include <cstdint>

#define NN 50000
#define NE 800000
#define HID 128
#define HEADS 4
#define HD 512  // HEADS*HID
#define NEG 0.2f
#define NBLK ((NN + 255) / 256)

// ---------------- scratch (device globals; no allocation allowed) ----------------
// g_aggx holds TWO bf16 arrays [NN*512] each (hi | lo)
__device__ __nv_bfloat16 g_axh[(size_t)NN * HD];
__device__ __nv_bfloat16 g_axl[(size_t)NN * HD];
// relu(conv) as bf16 hi/lo [NN*128]
__device__ __nv_bfloat16 g_cvh[(size_t)NN * HID];
__device__ __nv_bfloat16 g_cvl[(size_t)NN * HID];
__device__ float g_asrc[NN * HEADS];
__device__ float g_adst[NN * HEADS];
__device__ float g_tmp[(size_t)NN * HID];     // layer-0 output features (fp32)
__device__ float g_va[2 * 2 * HEADS * HID];   // folded attention vectors [l][s/d][h][k]
__device__ int   g_rowptr[NN + 1];
__device__ int   g_deg[NN];
__device__ int   g_srcs[NE];
__device__ int   g_bsum[NBLK];
__device__ int   g_is64;
// transposed + bf16-split weights: per layer 768 rows (512 conv(*0.25) | 128 proj | 128 skip) x 128 k
__device__ __nv_bfloat16 g_wth[2 * 768 * 128];
__device__ __nv_bfloat16 g_wtl[2 * 768 * 128];

__device__ __forceinline__ uint32_t smem_u32(const void* p) {
    uint32_t a;
    asm("{ .reg .u64 t; cvta.to.shared.u64 t, %1; cvt.u32.u64 %0, t; }" : "=r"(a) : "l"(p));
    return a;
}

#define LDM_X4(r0, r1, r2, r3, addr) \
    asm volatile("ldmatrix.sync.aligned.m8n8.x4.shared.b16 {%0,%1,%2,%3}, [%4];" \
        : "=r"(r0), "=r"(r1), "=r"(r2), "=r"(r3) : "r"(addr))

#define MMA_BF16(c, a, b) \
    asm volatile("mma.sync.aligned.m16n8k16.row.col.f32.bf16.bf16.f32 " \
        "{%0,%1,%2,%3}, {%4,%5,%6,%7}, {%8,%9}, {%0,%1,%2,%3};" \
        : "+f"((c)[0]), "+f"((c)[1]), "+f"((c)[2]), "+f"((c)[3]) \
        : "r"((a)[0]), "r"((a)[1]), "r"((a)[2]), "r"((a)[3]), "r"((b)[0]), "r"((b)[1]))

__device__ __forceinline__ uint32_t pack_bf2(__nv_bfloat16 a, __nv_bfloat16 b) {
    return (uint32_t)__bfloat16_as_ushort(a) | ((uint32_t)__bfloat16_as_ushort(b) << 16);
}
__device__ __forceinline__ float leaky(float a) { return a >= 0.f ? a : NEG * a; }

// ---------------- prep: zero degree + edge dtype detection ----------------
__global__ void k_init(const unsigned int* p) {
    if (blockIdx.x < NBLK) {
        int i = blockIdx.x * 256 + threadIdx.x;
        if (i < NN) g_deg[i] = 0;
    } else {
        __shared__ unsigned int acc;
        if (threadIdx.x == 0) acc = 0u;
        __syncthreads();
        unsigned int v = 0u;
        for (int i = threadIdx.x; i < 4096; i += 256) v |= p[2 * i + 1];
        atomicOr(&acc, v);
        __syncthreads();
        if (threadIdx.x == 0) g_is64 = (acc == 0u) ? 1 : 0;
    }
}
__device__ __forceinline__ int edge_val(const void* ei, int idx) {
    if (g_is64) return (int)((const long long*)ei)[idx];
    return ((const int*)ei)[idx];
}

// ---------------- CSR build ----------------
__global__ void k_degree(const void* ei) {
    int e = blockIdx.x * blockDim.x + threadIdx.x;
    if (e >= NE) return;
    atomicAdd(&g_deg[edge_val(ei, NE + e)], 1);
}
__device__ __forceinline__ int warp_incl_scan(int x, int lane) {
#pragma unroll
    for (int o = 1; o < 32; o <<= 1) {
        int y = __shfl_up_sync(0xffffffffu, x, o);
        if (lane >= o) x += y;
    }
    return x;
}
__global__ void k_scan1() {
    int b = blockIdx.x, t = threadIdx.x, i = b * 256 + t;
    int lane = t & 31, w = t >> 5;
    int v = (i < NN) ? g_deg[i] : 0;
    int x = warp_incl_scan(v, lane);
    __shared__ int ws[8];
    if (lane == 31) ws[w] = x;
    __syncthreads();
    int add = 0;
#pragma unroll
    for (int j = 0; j < 8; j++) if (j < w) add += ws[j];
    int incl = x + add;
    if (i < NN) g_rowptr[i] = incl - v;
    if (t == 255) g_bsum[b] = incl;
}
__global__ void k_scan2() {
    int t = threadIdx.x, lane = t & 31, w = t >> 5;
    int v = (t < NBLK) ? g_bsum[t] : 0;
    int x = warp_incl_scan(v, lane);
    __shared__ int ws[8];
    if (lane == 31) ws[w] = x;
    __syncthreads();
    int add = 0;
#pragma unroll
    for (int j = 0; j < 8; j++) if (j < w) add += ws[j];
    if (t < NBLK) g_bsum[t] = x + add - v;
}
__global__ void k_scan3() {
    int i = blockIdx.x * blockDim.x + threadIdx.x;
    if (i < NN) { g_rowptr[i] += g_bsum[i >> 8]; g_deg[i] = 0; }
    if (i == 0) g_rowptr[NN] = NE;
}
__global__ void k_bucket(const void* ei) {
    int e = blockIdx.x * blockDim.x + threadIdx.x;
    if (e >= NE) return;
    int s = edge_val(ei, e);
    int d = edge_val(ei, NE + e);
    int pos = atomicAdd(&g_deg[d], 1);
    g_srcs[g_rowptr[d] + pos] = s;
}

// ---------------- weight prep: transpose+split AND folded attention vectors ----------------
__global__ void k_wprep(const float* __restrict__ conv_w, const float* __restrict__ proj_w,
                        const float* __restrict__ skip_w, const float* __restrict__ att_src,
                        const float* __restrict__ att_dst) {
    if (blockIdx.x < 768) {
        int i = blockIdx.x * 256 + threadIdx.x;
        int l = i / 98304, r = i % 98304;
        int row = r >> 7, k = r & 127;
        float v;
        if (row < 512)       v = conv_w[l * 65536 + k * 512 + row] * 0.25f;  // fold head-mean
        else if (row < 640)  v = proj_w[l * 16384 + k * 128 + (row - 512)];
        else                 v = skip_w[l * 16384 + k * 128 + (row - 640)];
        __nv_bfloat16 hi = __float2bfloat16(v);
        __nv_bfloat16 lo = __float2bfloat16(v - __bfloat162float(hi));
        g_wth[i] = hi;
        g_wtl[i] = lo;
    } else {
        int idx = (blockIdx.x - 768) * 256 + threadIdx.x;   // 2048 outputs
        if (idx >= 2048) return;
        int l = idx >> 10, r = idx & 1023;
        int sd = r >> 9, h = (r >> 7) & 3, k = r & 127;
        const float* w = conv_w + l * 65536 + k * 512 + h * 128;
        const float* a = (sd ? att_dst : att_src) + l * 512 + h * 128;
        float s = 0.f;
#pragma unroll
        for (int c = 0; c < 128; c += 4) {
            float4 wv = *(const float4*)(w + c);
            float4 av = *(const float4*)(a + c);
            s += wv.x * av.x + wv.y * av.y + wv.z * av.z + wv.w * av.w;
        }
        g_va[idx] = s;
    }
}

// ---------------- attention logits from feat directly: warp per node ----------------
__global__ void k_alpha_x(const float* __restrict__ feat, const float* __restrict__ va) {
    int n = (blockIdx.x * blockDim.x + threadIdx.x) >> 5;
    if (n >= NN) return;
    int lane = threadIdx.x & 31;
    float4 xv = *(const float4*)(feat + (size_t)n * HID + lane * 4);
#pragma unroll
    for (int h = 0; h < HEADS; h++) {
        float4 s4 = *(const float4*)(va + h * 128 + lane * 4);
        float4 d4 = *(const float4*)(va + 512 + h * 128 + lane * 4);
        float s1 = xv.x * s4.x + xv.y * s4.y + xv.z * s4.z + xv.w * s4.w;
        float s2 = xv.x * d4.x + xv.y * d4.y + xv.z * d4.z + xv.w * d4.w;
#pragma unroll
        for (int off = 16; off; off >>= 1) {
            s1 += __shfl_xor_sync(0xffffffffu, s1, off);
            s2 += __shfl_xor_sync(0xffffffffu, s2, off);
        }
        if (lane == 0) {
            g_asrc[n * HEADS + h] = s1;
            g_adst[n * HEADS + h] = s2;
        }
    }
}

// ---------------- fused softmax + x-aggregation: warp per node ----------------
// Output written directly as bf16 hi/lo pairs into g_axh/g_axl [N,512].
__global__ void k_edge(const float* __restrict__ feat) {
    int n = (blockIdx.x * blockDim.x + threadIdx.x) >> 5;
    if (n >= NN) return;
    int lane = threadIdx.x & 31;
    int b = g_rowptr[n], e = g_rowptr[n + 1];
    float4 ad = *(const float4*)(g_adst + n * 4);

    // pass 1: per-head max
    float m0 = -3.4e38f, m1 = m0, m2 = m0, m3 = m0;
    for (int i = b + lane; i < e; i += 32) {
        int s = g_srcs[i];
        float4 as = *(const float4*)(g_asrc + s * 4);
        m0 = fmaxf(m0, leaky(as.x + ad.x));
        m1 = fmaxf(m1, leaky(as.y + ad.y));
        m2 = fmaxf(m2, leaky(as.z + ad.z));
        m3 = fmaxf(m3, leaky(as.w + ad.w));
    }
#pragma unroll
    for (int off = 16; off; off >>= 1) {
        m0 = fmaxf(m0, __shfl_xor_sync(0xffffffffu, m0, off));
        m1 = fmaxf(m1, __shfl_xor_sync(0xffffffffu, m1, off));
        m2 = fmaxf(m2, __shfl_xor_sync(0xffffffffu, m2, off));
        m3 = fmaxf(m3, __shfl_xor_sync(0xffffffffu, m3, off));
    }

    // pass 2: exp weights (lane-parallel) broadcast into warp-uniform x gather
    float d0 = 0.f, d1 = 0.f, d2 = 0.f, d3 = 0.f;
    float4 a0 = {0, 0, 0, 0}, a1 = a0, a2 = a0, a3 = a0;
    for (int base = b; base < e; base += 32) {
        int i = base + lane;
        float wx = 0.f, wy = 0.f, wz = 0.f, ww = 0.f;
        int sreg = 0;
        if (i < e) {
            sreg = g_srcs[i];
            float4 as = *(const float4*)(g_asrc + sreg * 4);
            wx = __expf(leaky(as.x + ad.x) - m0); d0 += wx;
            wy = __expf(leaky(as.y + ad.y) - m1); d1 += wy;
            wz = __expf(leaky(as.z + ad.z) - m2); d2 += wz;
            ww = __expf(leaky(as.w + ad.w) - m3); d3 += ww;
        }
        int cnt = min(32, e - base);
#pragma unroll 4
        for (int j = 0; j < cnt; j++) {
            int s   = __shfl_sync(0xffffffffu, sreg, j);
            float w0 = __shfl_sync(0xffffffffu, wx, j);
            float w1 = __shfl_sync(0xffffffffu, wy, j);
            float w2 = __shfl_sync(0xffffffffu, wz, j);
            float w3 = __shfl_sync(0xffffffffu, ww, j);
            float4 xv = *(const float4*)(feat + (size_t)s * HID + lane * 4);
            a0.x = fmaf(w0, xv.x, a0.x); a0.y = fmaf(w0, xv.y, a0.y);
            a0.z = fmaf(w0, xv.z, a0.z); a0.w = fmaf(w0, xv.w, a0.w);
            a1.x = fmaf(w1, xv.x, a1.x); a1.y = fmaf(w1, xv.y, a1.y);
            a1.z = fmaf(w1, xv.z, a1.z); a1.w = fmaf(w1, xv.w, a1.w);
            a2.x = fmaf(w2, xv.x, a2.x); a2.y = fmaf(w2, xv.y, a2.y);
            a2.z = fmaf(w2, xv.z, a2.z); a2.w = fmaf(w2, xv.w, a2.w);
            a3.x = fmaf(w3, xv.x, a3.x); a3.y = fmaf(w3, xv.y, a3.y);
            a3.z = fmaf(w3, xv.z, a3.z); a3.w = fmaf(w3, xv.w, a3.w);
        }
    }
#pragma unroll
    for (int off = 16; off; off >>= 1) {
        d0 += __shfl_xor_sync(0xffffffffu, d0, off);
        d1 += __shfl_xor_sync(0xffffffffu, d1, off);
        d2 += __shfl_xor_sync(0xffffffffu, d2, off);
        d3 += __shfl_xor_sync(0xffffffffu, d3, off);
    }
    float i0 = 1.f / (d0 + 1e-16f), i1 = 1.f / (d1 + 1e-16f);
    float i2 = 1.f / (d2 + 1e-16f), i3 = 1.f / (d3 + 1e-16f);

    // normalize + bf16 hi/lo split + store
    float4 o[4];
    o[0] = make_float4(a0.x * i0, a0.y * i0, a0.z * i0, a0.w * i0);
    o[1] = make_float4(a1.x * i1, a1.y * i1, a1.z * i1, a1.w * i1);
    o[2] = make_float4(a2.x * i2, a2.y * i2, a2.z * i2, a2.w * i2);
    o[3] = make_float4(a3.x * i3, a3.y * i3, a3.z * i3, a3.w * i3);
#pragma unroll
    for (int h = 0; h < 4; h++) {
        float f[4] = {o[h].x, o[h].y, o[h].z, o[h].w};
        __nv_bfloat16 hi[4];
        __nv_bfloat16 lo[4];
#pragma unroll
        for (int j = 0; j < 4; j++) {
            hi[j] = __float2bfloat16(f[j]);
            lo[j] = __float2bfloat16(f[j] - __bfloat162float(hi[j]));
        }
        uint2 uh = {pack_bf2(hi[0], hi[1]), pack_bf2(hi[2], hi[3])};
        uint2 ul = {pack_bf2(lo[0], lo[1]), pack_bf2(lo[2], lo[3])};
        size_t off = (size_t)n * HD + h * HID + lane * 4;
        *(uint2*)(g_axh + off) = uh;
        *(uint2*)(g_axl + off) = ul;
    }
}

// ================= HMMA split-bf16 GEMM =================
#define TILE_STRIDE 272            // (128+8) bf16 per row
#define TILE_BYTES  (128 * TILE_STRIDE)
#define SM_BIAS 0
#define SM_TILE 1024
#define SM_TOT  (SM_TILE + 4 * TILE_BYTES)   // 140288 B

// MODE 0 (conv): NCHUNK k-chunks from pre-split bf16 A (row stride ldab, col offset ch*128);
//                epilogue writes relu(c+bias) as bf16 hi/lo to Ch/Cl.
// MODE 1 (proj+skip): chunk0 = pre-split bf16 A (ldab), chunk1 = fp32 Af (stride 128) converted;
//                epilogue writes fp32 c+bias to C.
template <int NCHUNK, int MODE>
__global__ __launch_bounds__(256, 1) void k_hmma(
    const __nv_bfloat16* __restrict__ Ah, const __nv_bfloat16* __restrict__ Al, int ldab,
    const float* __restrict__ Af,
    const __nv_bfloat16* __restrict__ Bh, const __nv_bfloat16* __restrict__ Bl,
    float* __restrict__ C, __nv_bfloat16* __restrict__ Ch, __nv_bfloat16* __restrict__ Cl,
    const float* __restrict__ bias, const float* __restrict__ bias2, int M)
{
    extern __shared__ char sm[];
    uint32_t smb = smem_u32(sm);
    const uint32_t uAh = smb + SM_TILE;
    const uint32_t uAl = uAh + TILE_BYTES;
    const uint32_t uBh = uAl + TILE_BYTES;
    const uint32_t uBl = uBh + TILE_BYTES;
    float* sBias = (float*)(sm + SM_BIAS);

    int t = threadIdx.x, lane = t & 31, wid = t >> 5;
    int bm = blockIdx.y * 128;

    if (t < 128) {
        float bv = bias ? bias[t] : 0.f;
        if (bias2) bv += bias2[t];
        sBias[t] = bv;
    }

    int wm = (wid >> 2) * 64, wn = (wid & 3) * 32;
    const uint32_t aOff = (uint32_t)((wm + (lane & 7) + (lane & 8)) * TILE_STRIDE + ((lane & 16) ? 16 : 0));
    const uint32_t bOff = (uint32_t)((wn + (lane & 7) + ((lane & 16) ? 8 : 0)) * TILE_STRIDE + ((lane & 8) ? 16 : 0));

    float c[4][4][4];
#pragma unroll
    for (int i = 0; i < 4; i++)
#pragma unroll
        for (int j = 0; j < 4; j++)
#pragma unroll
            for (int k = 0; k < 4; k++) c[i][j][k] = 0.f;

#pragma unroll
    for (int ch = 0; ch < NCHUNK; ch++) {
        if (MODE == 0 || ch == 0) {
            // ---- A: pre-split bf16 pair copy ----
            const __nv_bfloat16* ah = Ah + (MODE == 0 ? ch * 128 : 0);
            const __nv_bfloat16* al = Al + (MODE == 0 ? ch * 128 : 0);
#pragma unroll
            for (int i = 0; i < 8; i++) {
                int idx = t + i * 256;
                int r = idx >> 4, kc = idx & 15;
                int m = bm + r;
                uint4 vh, vl;
                if (m < M) {
                    vh = *(const uint4*)(ah + (size_t)m * ldab + kc * 8);
                    vl = *(const uint4*)(al + (size_t)m * ldab + kc * 8);
                } else {
                    vh = make_uint4(0, 0, 0, 0); vl = vh;
                }
                uint32_t off = (uint32_t)(r * TILE_STRIDE + kc * 16);
                *(uint4*)(sm + SM_TILE + off) = vh;
                *(uint4*)(sm + SM_TILE + TILE_BYTES + off) = vl;
            }
        } else {
            // ---- A: fp32 -> bf16 hi/lo convert (feat chunk) ----
#pragma unroll
            for (int i = 0; i < 8; i++) {
                int idx = t + i * 256;
                int r = idx >> 4, kc = idx & 15;
                int m = bm + r;
                float4 v0, v1;
                if (m < M) {
                    const float4* p = (const float4*)(Af + (size_t)m * HID + kc * 8);
                    v0 = p[0]; v1 = p[1];
                } else {
                    v0 = make_float4(0.f, 0.f, 0.f, 0.f); v1 = v0;
                }
                float f[8] = {v0.x, v0.y, v0.z, v0.w, v1.x, v1.y, v1.z, v1.w};
                uint4 uh, ul;
                uint32_t* ph = (uint32_t*)&uh;
                uint32_t* pl = (uint32_t*)&ul;
#pragma unroll
                for (int j = 0; j < 4; j++) {
                    float a = f[2 * j], b2 = f[2 * j + 1];
                    __nv_bfloat16 ha = __float2bfloat16(a), hb = __float2bfloat16(b2);
                    __nv_bfloat16 la = __float2bfloat16(a - __bfloat162float(ha));
                    __nv_bfloat16 lb = __float2bfloat16(b2 - __bfloat162float(hb));
                    ph[j] = pack_bf2(ha, hb);
                    pl[j] = pack_bf2(la, lb);
                }
                uint32_t off = (uint32_t)(r * TILE_STRIDE + kc * 16);
                *(uint4*)(sm + SM_TILE + off) = uh;
                *(uint4*)(sm + SM_TILE + TILE_BYTES + off) = ul;
            }
        }
        // ---- B: bf16 hi/lo copy ----
        {
            const __nv_bfloat16* bh = Bh + (size_t)ch * 16384;
            const __nv_bfloat16* bl = Bl + (size_t)ch * 16384;
#pragma unroll
            for (int i = 0; i < 8; i++) {
                int idx = t + i * 256;
                int r = idx >> 4, kc = idx & 15;
                uint4 vh = *(const uint4*)(bh + r * 128 + kc * 8);
                uint4 vl = *(const uint4*)(bl + r * 128 + kc * 8);
                uint32_t off = (uint32_t)(r * TILE_STRIDE + kc * 16);
                *(uint4*)(sm + SM_TILE + 2 * TILE_BYTES + off) = vh;
                *(uint4*)(sm + SM_TILE + 3 * TILE_BYTES + off) = vl;
            }
        }
        __syncthreads();

        // ---- 3 precision passes: Ah*Bh, Ah*Bl, Al*Bh ----
#pragma unroll
        for (int pass = 0; pass < 3; pass++) {
            uint32_t aBase = ((pass == 2) ? uAl : uAh) + aOff;
            uint32_t bBase = ((pass == 1) ? uBl : uBh) + bOff;
#pragma unroll
            for (int k0 = 0; k0 < 8; k0++) {
                uint32_t ka = aBase + k0 * 32;
                uint32_t kb = bBase + k0 * 32;
                uint32_t a[4][4], b[4][2];
#pragma unroll
                for (int mt = 0; mt < 4; mt++)
                    LDM_X4(a[mt][0], a[mt][1], a[mt][2], a[mt][3], ka + mt * 16 * TILE_STRIDE);
#pragma unroll
                for (int np = 0; np < 2; np++)
                    LDM_X4(b[2 * np][0], b[2 * np][1], b[2 * np + 1][0], b[2 * np + 1][1],
                           kb + np * 16 * TILE_STRIDE);
#pragma unroll
                for (int mt = 0; mt < 4; mt++)
#pragma unroll
                    for (int nt = 0; nt < 4; nt++)
                        MMA_BF16(c[mt][nt], a[mt], b[nt]);
            }
        }
        if (ch + 1 < NCHUNK) __syncthreads();
    }

    // ---- epilogue ----
    int g = lane >> 2, t2 = (lane & 3) * 2;
#pragma unroll
    for (int mt = 0; mt < 4; mt++) {
        int r0 = wm + mt * 16 + g;
        int m0 = bm + r0, m1 = m0 + 8;
#pragma unroll
        for (int nt = 0; nt < 4; nt++) {
            int col = wn + nt * 8 + t2;
            float bb0 = sBias[col], bb1 = sBias[col + 1];
            if (MODE == 0) {
                // relu + bf16 hi/lo split
                if (m0 < M) {
                    float o0 = fmaxf(c[mt][nt][0] + bb0, 0.f);
                    float o1 = fmaxf(c[mt][nt][1] + bb1, 0.f);
                    __nv_bfloat16 h0 = __float2bfloat16(o0), h1 = __float2bfloat16(o1);
                    __nv_bfloat16 l0 = __float2bfloat16(o0 - __bfloat162float(h0));
                    __nv_bfloat16 l1 = __float2bfloat16(o1 - __bfloat162float(h1));
                    *(uint32_t*)(Ch + (size_t)m0 * HID + col) = pack_bf2(h0, h1);
                    *(uint32_t*)(Cl + (size_t)m0 * HID + col) = pack_bf2(l0, l1);
                }
                if (m1 < M) {
                    float o0 = fmaxf(c[mt][nt][2] + bb0, 0.f);
                    float o1 = fmaxf(c[mt][nt][3] + bb1, 0.f);
                    __nv_bfloat16 h0 = __float2bfloat16(o0), h1 = __float2bfloat16(o1);
                    __nv_bfloat16 l0 = __float2bfloat16(o0 - __bfloat162float(h0));
                    __nv_bfloat16 l1 = __float2bfloat16(o1 - __bfloat162float(h1));
                    *(uint32_t*)(Ch + (size_t)m1 * HID + col) = pack_bf2(h0, h1);
                    *(uint32_t*)(Cl + (size_t)m1 * HID + col) = pack_bf2(l0, l1);
                }
            } else {
                if (m0 < M) {
                    float2 o = {c[mt][nt][0] + bb0, c[mt][nt][1] + bb1};
                    *(float2*)(C + (size_t)m0 * HID + col) = o;
                }
                if (m1 < M) {
                    float2 o = {c[mt][nt][2] + bb0, c[mt][nt][3] + bb1};
                    *(float2*)(C + (size_t)m1 * HID + col) = o;
                }
            }
        }
    }
}

// ---------------- host orchestration ----------------
extern "C" void kernel_launch(void* const* d_in, const int* in_sizes, int n_in,
                              void* d_out, int out_size) {
    const float* x       = (const float*)d_in[0];
    const void*  ei      = d_in[1];
    const float* conv_w  = (const float*)d_in[2];
    const float* att_src = (const float*)d_in[3];
    const float* att_dst = (const float*)d_in[4];
    const float* conv_b  = (const float*)d_in[5];
    const float* proj_w  = (const float*)d_in[6];
    const float* proj_b  = (const float*)d_in[7];
    const float* skip_w  = (const float*)d_in[8];
    const float* skip_b  = (const float*)d_in[9];
    float* out = (float*)d_out;

    float *p_tmp, *p_va;
    __nv_bfloat16 *p_wth, *p_wtl, *p_axh, *p_axl, *p_cvh, *p_cvl;
    cudaGetSymbolAddress((void**)&p_tmp, g_tmp);
    cudaGetSymbolAddress((void**)&p_va, g_va);
    cudaGetSymbolAddress((void**)&p_wth, g_wth);
    cudaGetSymbolAddress((void**)&p_wtl, g_wtl);
    cudaGetSymbolAddress((void**)&p_axh, g_axh);
    cudaGetSymbolAddress((void**)&p_axl, g_axl);
    cudaGetSymbolAddress((void**)&p_cvh, g_cvh);
    cudaGetSymbolAddress((void**)&p_cvl, g_cvl);

    cudaFuncSetAttribute(k_hmma<4, 0>, cudaFuncAttributeMaxDynamicSharedMemorySize, SM_TOT);
    cudaFuncSetAttribute(k_hmma<2, 1>, cudaFuncAttributeMaxDynamicSharedMemorySize, SM_TOT);

    // CSR build + weight prep (once per call)
    k_init<<<NBLK + 1, 256>>>((const unsigned int*)ei);
    k_degree<<<(NE + 255) / 256, 256>>>(ei);
    k_scan1<<<NBLK, 256>>>();
    k_scan2<<<1, 256>>>();
    k_scan3<<<NBLK, 256>>>();
    k_bucket<<<(NE + 255) / 256, 256>>>(ei);
    k_wprep<<<776, 256>>>(conv_w, proj_w, skip_w, att_src, att_dst);

    const float* feat = x;
    const int NWB = (NN + 7) / 8;     // warp-per-node blocks at 256 threads
    const int MT = (NN + 127) / 128;  // 391 M-tiles
    for (int l = 0; l < 2; l++) {
        float* lout = (l == 0) ? p_tmp : out;
        const __nv_bfloat16* wh = p_wth + (size_t)l * 98304;
        const __nv_bfloat16* wl = p_wtl + (size_t)l * 98304;
        // attention logits directly from feat (folded vectors)
        k_alpha_x<<<NWB, 256>>>(feat, p_va + l * 1024);
        // fused softmax + x-space aggregation -> bf16 pair output
        k_edge<<<NWB, 256>>>(feat);
        // conv = relu(aggx @ 0.25*Wstack + conv_b) -> bf16 pairs   (K=512)
        dim3 gc(1, MT);
        k_hmma<4, 0><<<gc, 256, SM_TOT>>>(
            p_axh, p_axl, HD, nullptr, wh, wl,
            nullptr, p_cvh, p_cvl, conv_b + l * HID, nullptr, NN);
        // out = relu(conv) @ proj_w + proj_b + feat @ skip_w + skip_b   (K=256)
        k_hmma<2, 1><<<gc, 256, SM_TOT>>>(
            p_cvh, p_cvl, HID, feat, wh + 65536, wl + 65536,
            lout, nullptr, nullptr, proj_b + l * HID, skip_b + l * HID, NN);
        feat = p_tmp;
    }
}

// round 16
// speedup vs baseline: 1.1223x; 1.1223x over previous
#include <cuda_runtime.h>
#include <cuda_bf16.h>
#include <cstdint>

#define NN 50000
#define NE 800000
#define HID 128
#define HEADS 4
#define HD 512  // HEADS*HID
#define NEG 0.2f
#define NBLK ((NN + 255) / 256)

// ---------------- scratch (device globals; no allocation allowed) ----------------
__device__ __nv_bfloat16 g_axh[(size_t)NN * HD];   // aggregated x, bf16 hi
__device__ __nv_bfloat16 g_axl[(size_t)NN * HD];   // aggregated x, bf16 lo
__device__ float g_asrc[NN * HEADS];
__device__ float g_adst[NN * HEADS];
__device__ float g_tmp[(size_t)NN * HID];     // layer-0 output features (fp32)
__device__ float g_va[2 * 2 * HEADS * HID];   // folded attention vectors [l][s/d][h][k]
__device__ int   g_rowptr[NN + 1];
__device__ int   g_deg[NN];
__device__ int   g_srcs[NE];
__device__ int   g_bsum[NBLK];
__device__ int   g_is64;
// transposed + bf16-split weights: per layer 768 rows (512 conv(*0.25) | 128 proj | 128 skip) x 128 k
__device__ __nv_bfloat16 g_wth[2 * 768 * 128];
__device__ __nv_bfloat16 g_wtl[2 * 768 * 128];

__device__ __forceinline__ uint32_t smem_u32(const void* p) {
    uint32_t a;
    asm("{ .reg .u64 t; cvta.to.shared.u64 t, %1; cvt.u32.u64 %0, t; }" : "=r"(a) : "l"(p));
    return a;
}

#define LDM_X4(r0, r1, r2, r3, addr) \
    asm volatile("ldmatrix.sync.aligned.m8n8.x4.shared.b16 {%0,%1,%2,%3}, [%4];" \
        : "=r"(r0), "=r"(r1), "=r"(r2), "=r"(r3) : "r"(addr))

#define MMA_BF16(c, a, b) \
    asm volatile("mma.sync.aligned.m16n8k16.row.col.f32.bf16.bf16.f32 " \
        "{%0,%1,%2,%3}, {%4,%5,%6,%7}, {%8,%9}, {%0,%1,%2,%3};" \
        : "+f"((c)[0]), "+f"((c)[1]), "+f"((c)[2]), "+f"((c)[3]) \
        : "r"((a)[0]), "r"((a)[1]), "r"((a)[2]), "r"((a)[3]), "r"((b)[0]), "r"((b)[1]))

__device__ __forceinline__ uint32_t pack_bf2(__nv_bfloat16 a, __nv_bfloat16 b) {
    return (uint32_t)__bfloat16_as_ushort(a) | ((uint32_t)__bfloat16_as_ushort(b) << 16);
}
__device__ __forceinline__ float leaky(float a) { return a >= 0.f ? a : NEG * a; }

// ---------------- prep: zero degree + edge dtype detection ----------------
__global__ void k_init(const unsigned int* p) {
    if (blockIdx.x < NBLK) {
        int i = blockIdx.x * 256 + threadIdx.x;
        if (i < NN) g_deg[i] = 0;
    } else {
        __shared__ unsigned int acc;
        if (threadIdx.x == 0) acc = 0u;
        __syncthreads();
        unsigned int v = 0u;
        for (int i = threadIdx.x; i < 4096; i += 256) v |= p[2 * i + 1];
        atomicOr(&acc, v);
        __syncthreads();
        if (threadIdx.x == 0) g_is64 = (acc == 0u) ? 1 : 0;
    }
}
__device__ __forceinline__ int edge_val(const void* ei, int idx) {
    if (g_is64) return (int)((const long long*)ei)[idx];
    return ((const int*)ei)[idx];
}

// ---------------- CSR build ----------------
__global__ void k_degree(const void* ei) {
    int e = blockIdx.x * blockDim.x + threadIdx.x;
    if (e >= NE) return;
    atomicAdd(&g_deg[edge_val(ei, NE + e)], 1);
}
__device__ __forceinline__ int warp_incl_scan(int x, int lane) {
#pragma unroll
    for (int o = 1; o < 32; o <<= 1) {
        int y = __shfl_up_sync(0xffffffffu, x, o);
        if (lane >= o) x += y;
    }
    return x;
}
__global__ void k_scan1() {
    int b = blockIdx.x, t = threadIdx.x, i = b * 256 + t;
    int lane = t & 31, w = t >> 5;
    int v = (i < NN) ? g_deg[i] : 0;
    int x = warp_incl_scan(v, lane);
    __shared__ int ws[8];
    if (lane == 31) ws[w] = x;
    __syncthreads();
    int add = 0;
#pragma unroll
    for (int j = 0; j < 8; j++) if (j < w) add += ws[j];
    int incl = x + add;
    if (i < NN) g_rowptr[i] = incl - v;
    if (t == 255) g_bsum[b] = incl;
}
__global__ void k_scan2() {
    int t = threadIdx.x, lane = t & 31, w = t >> 5;
    int v = (t < NBLK) ? g_bsum[t] : 0;
    int x = warp_incl_scan(v, lane);
    __shared__ int ws[8];
    if (lane == 31) ws[w] = x;
    __syncthreads();
    int add = 0;
#pragma unroll
    for (int j = 0; j < 8; j++) if (j < w) add += ws[j];
    if (t < NBLK) g_bsum[t] = x + add - v;
}
__global__ void k_scan3() {
    int i = blockIdx.x * blockDim.x + threadIdx.x;
    if (i < NN) { g_rowptr[i] += g_bsum[i >> 8]; g_deg[i] = 0; }
    if (i == 0) g_rowptr[NN] = NE;
}
__global__ void k_bucket(const void* ei) {
    int e = blockIdx.x * blockDim.x + threadIdx.x;
    if (e >= NE) return;
    int s = edge_val(ei, e);
    int d = edge_val(ei, NE + e);
    int pos = atomicAdd(&g_deg[d], 1);
    g_srcs[g_rowptr[d] + pos] = s;
}

// ---------------- weight prep: transpose+split AND folded attention vectors ----------------
__global__ void k_wprep(const float* __restrict__ conv_w, const float* __restrict__ proj_w,
                        const float* __restrict__ skip_w, const float* __restrict__ att_src,
                        const float* __restrict__ att_dst) {
    if (blockIdx.x < 768) {
        int i = blockIdx.x * 256 + threadIdx.x;
        int l = i / 98304, r = i % 98304;
        int row = r >> 7, k = r & 127;
        float v;
        if (row < 512)       v = conv_w[l * 65536 + k * 512 + row] * 0.25f;  // fold head-mean
        else if (row < 640)  v = proj_w[l * 16384 + k * 128 + (row - 512)];
        else                 v = skip_w[l * 16384 + k * 128 + (row - 640)];
        __nv_bfloat16 hi = __float2bfloat16(v);
        __nv_bfloat16 lo = __float2bfloat16(v - __bfloat162float(hi));
        g_wth[i] = hi;
        g_wtl[i] = lo;
    } else {
        int idx = (blockIdx.x - 768) * 256 + threadIdx.x;   // 2048 outputs
        if (idx >= 2048) return;
        int l = idx >> 10, r = idx & 1023;
        int sd = r >> 9, h = (r >> 7) & 3, k = r & 127;
        const float* w = conv_w + l * 65536 + k * 512 + h * 128;
        const float* a = (sd ? att_dst : att_src) + l * 512 + h * 128;
        float s = 0.f;
#pragma unroll
        for (int c = 0; c < 128; c += 4) {
            float4 wv = *(const float4*)(w + c);
            float4 av = *(const float4*)(a + c);
            s += wv.x * av.x + wv.y * av.y + wv.z * av.z + wv.w * av.w;
        }
        g_va[idx] = s;
    }
}

// ---------------- attention logits from feat directly: warp per node ----------------
__global__ void k_alpha_x(const float* __restrict__ feat, const float* __restrict__ va) {
    int n = (blockIdx.x * blockDim.x + threadIdx.x) >> 5;
    if (n >= NN) return;
    int lane = threadIdx.x & 31;
    float4 xv = *(const float4*)(feat + (size_t)n * HID + lane * 4);
#pragma unroll
    for (int h = 0; h < HEADS; h++) {
        float4 s4 = *(const float4*)(va + h * 128 + lane * 4);
        float4 d4 = *(const float4*)(va + 512 + h * 128 + lane * 4);
        float s1 = xv.x * s4.x + xv.y * s4.y + xv.z * s4.z + xv.w * s4.w;
        float s2 = xv.x * d4.x + xv.y * d4.y + xv.z * d4.z + xv.w * d4.w;
#pragma unroll
        for (int off = 16; off; off >>= 1) {
            s1 += __shfl_xor_sync(0xffffffffu, s1, off);
            s2 += __shfl_xor_sync(0xffffffffu, s2, off);
        }
        if (lane == 0) {
            g_asrc[n * HEADS + h] = s1;
            g_adst[n * HEADS + h] = s2;
        }
    }
}

// ---------------- fused softmax + x-aggregation: warp per node, smem edge staging ----------------
__global__ void k_edge(const float* __restrict__ feat) {
    __shared__ int    s_src[8][32];
    __shared__ float4 s_w[8][32];
    int n = (blockIdx.x * blockDim.x + threadIdx.x) >> 5;
    if (n >= NN) return;
    int lane = threadIdx.x & 31, wid = (threadIdx.x >> 5) & 7;
    int b = g_rowptr[n], e = g_rowptr[n + 1];
    int deg = e - b;
    float4 ad = *(const float4*)(g_adst + n * 4);

    float d0 = 0.f, d1 = 0.f, d2 = 0.f, d3 = 0.f;
    float4 a0 = {0, 0, 0, 0}, a1 = a0, a2 = a0, a3 = a0;

    if (deg <= 32) {
        // fast path: one gather, logits kept in registers
        int i = b + lane;
        bool valid = (i < e);
        int sreg = 0;
        float l0 = -3.4e38f, l1 = l0, l2 = l0, l3 = l0;
        if (valid) {
            sreg = g_srcs[i];
            float4 as = *(const float4*)(g_asrc + sreg * 4);
            l0 = leaky(as.x + ad.x); l1 = leaky(as.y + ad.y);
            l2 = leaky(as.z + ad.z); l3 = leaky(as.w + ad.w);
        }
        float m0 = l0, m1 = l1, m2 = l2, m3 = l3;
#pragma unroll
        for (int off = 16; off; off >>= 1) {
            m0 = fmaxf(m0, __shfl_xor_sync(0xffffffffu, m0, off));
            m1 = fmaxf(m1, __shfl_xor_sync(0xffffffffu, m1, off));
            m2 = fmaxf(m2, __shfl_xor_sync(0xffffffffu, m2, off));
            m3 = fmaxf(m3, __shfl_xor_sync(0xffffffffu, m3, off));
        }
        float w0 = 0.f, w1 = 0.f, w2 = 0.f, w3 = 0.f;
        if (valid) {
            w0 = __expf(l0 - m0); w1 = __expf(l1 - m1);
            w2 = __expf(l2 - m2); w3 = __expf(l3 - m3);
        }
        d0 = w0; d1 = w1; d2 = w2; d3 = w3;
        s_src[wid][lane] = sreg;
        s_w[wid][lane] = make_float4(w0, w1, w2, w3);
        __syncwarp();
        for (int j = 0; j < deg; j++) {
            int s = s_src[wid][j];
            float4 w = s_w[wid][j];
            float4 xv = *(const float4*)(feat + (size_t)s * HID + lane * 4);
            a0.x = fmaf(w.x, xv.x, a0.x); a0.y = fmaf(w.x, xv.y, a0.y);
            a0.z = fmaf(w.x, xv.z, a0.z); a0.w = fmaf(w.x, xv.w, a0.w);
            a1.x = fmaf(w.y, xv.x, a1.x); a1.y = fmaf(w.y, xv.y, a1.y);
            a1.z = fmaf(w.y, xv.z, a1.z); a1.w = fmaf(w.y, xv.w, a1.w);
            a2.x = fmaf(w.z, xv.x, a2.x); a2.y = fmaf(w.z, xv.y, a2.y);
            a2.z = fmaf(w.z, xv.z, a2.z); a2.w = fmaf(w.z, xv.w, a2.w);
            a3.x = fmaf(w.w, xv.x, a3.x); a3.y = fmaf(w.w, xv.y, a3.y);
            a3.z = fmaf(w.w, xv.z, a3.z); a3.w = fmaf(w.w, xv.w, a3.w);
        }
    } else {
        // slow path: two-pass
        float m0 = -3.4e38f, m1 = m0, m2 = m0, m3 = m0;
        for (int i = b + lane; i < e; i += 32) {
            int s = g_srcs[i];
            float4 as = *(const float4*)(g_asrc + s * 4);
            m0 = fmaxf(m0, leaky(as.x + ad.x));
            m1 = fmaxf(m1, leaky(as.y + ad.y));
            m2 = fmaxf(m2, leaky(as.z + ad.z));
            m3 = fmaxf(m3, leaky(as.w + ad.w));
        }
#pragma unroll
        for (int off = 16; off; off >>= 1) {
            m0 = fmaxf(m0, __shfl_xor_sync(0xffffffffu, m0, off));
            m1 = fmaxf(m1, __shfl_xor_sync(0xffffffffu, m1, off));
            m2 = fmaxf(m2, __shfl_xor_sync(0xffffffffu, m2, off));
            m3 = fmaxf(m3, __shfl_xor_sync(0xffffffffu, m3, off));
        }
        for (int base = b; base < e; base += 32) {
            int i = base + lane;
            float w0 = 0.f, w1 = 0.f, w2 = 0.f, w3 = 0.f;
            int sreg = 0;
            if (i < e) {
                sreg = g_srcs[i];
                float4 as = *(const float4*)(g_asrc + sreg * 4);
                w0 = __expf(leaky(as.x + ad.x) - m0); d0 += w0;
                w1 = __expf(leaky(as.y + ad.y) - m1); d1 += w1;
                w2 = __expf(leaky(as.z + ad.z) - m2); d2 += w2;
                w3 = __expf(leaky(as.w + ad.w) - m3); d3 += w3;
            }
            s_src[wid][lane] = sreg;
            s_w[wid][lane] = make_float4(w0, w1, w2, w3);
            __syncwarp();
            int cnt = min(32, e - base);
            for (int j = 0; j < cnt; j++) {
                int s = s_src[wid][j];
                float4 w = s_w[wid][j];
                float4 xv = *(const float4*)(feat + (size_t)s * HID + lane * 4);
                a0.x = fmaf(w.x, xv.x, a0.x); a0.y = fmaf(w.x, xv.y, a0.y);
                a0.z = fmaf(w.x, xv.z, a0.z); a0.w = fmaf(w.x, xv.w, a0.w);
                a1.x = fmaf(w.y, xv.x, a1.x); a1.y = fmaf(w.y, xv.y, a1.y);
                a1.z = fmaf(w.y, xv.z, a1.z); a1.w = fmaf(w.y, xv.w, a1.w);
                a2.x = fmaf(w.z, xv.x, a2.x); a2.y = fmaf(w.z, xv.y, a2.y);
                a2.z = fmaf(w.z, xv.z, a2.z); a2.w = fmaf(w.z, xv.w, a2.w);
                a3.x = fmaf(w.w, xv.x, a3.x); a3.y = fmaf(w.w, xv.y, a3.y);
                a3.z = fmaf(w.w, xv.z, a3.z); a3.w = fmaf(w.w, xv.w, a3.w);
            }
            __syncwarp();
        }
    }
#pragma unroll
    for (int off = 16; off; off >>= 1) {
        d0 += __shfl_xor_sync(0xffffffffu, d0, off);
        d1 += __shfl_xor_sync(0xffffffffu, d1, off);
        d2 += __shfl_xor_sync(0xffffffffu, d2, off);
        d3 += __shfl_xor_sync(0xffffffffu, d3, off);
    }
    float i0 = 1.f / (d0 + 1e-16f), i1 = 1.f / (d1 + 1e-16f);
    float i2 = 1.f / (d2 + 1e-16f), i3 = 1.f / (d3 + 1e-16f);

    float4 o[4];
    o[0] = make_float4(a0.x * i0, a0.y * i0, a0.z * i0, a0.w * i0);
    o[1] = make_float4(a1.x * i1, a1.y * i1, a1.z * i1, a1.w * i1);
    o[2] = make_float4(a2.x * i2, a2.y * i2, a2.z * i2, a2.w * i2);
    o[3] = make_float4(a3.x * i3, a3.y * i3, a3.z * i3, a3.w * i3);
#pragma unroll
    for (int h = 0; h < 4; h++) {
        float f[4] = {o[h].x, o[h].y, o[h].z, o[h].w};
        __nv_bfloat16 hi[4], lo[4];
#pragma unroll
        for (int j = 0; j < 4; j++) {
            hi[j] = __float2bfloat16(f[j]);
            lo[j] = __float2bfloat16(f[j] - __bfloat162float(hi[j]));
        }
        uint2 uh = {pack_bf2(hi[0], hi[1]), pack_bf2(hi[2], hi[3])};
        uint2 ul = {pack_bf2(lo[0], lo[1]), pack_bf2(lo[2], lo[3])};
        size_t off = (size_t)n * HD + h * HID + lane * 4;
        *(uint2*)(g_axh + off) = uh;
        *(uint2*)(g_axl + off) = ul;
    }
}

// ================= fused per-layer HMMA: conv(K=512) -> relu -> proj + skip (K=256) =================
#define TILE_STRIDE 272            // 272 bytes = 128 bf16 + 8 pad
#define TILE_BYTES  (128 * TILE_STRIDE)
#define SM_BIASC 0
#define SM_BIASO 512
#define SM_TILE 1024
#define SM_TOT  (SM_TILE + 4 * TILE_BYTES)   // 140288 B

__global__ __launch_bounds__(256, 1) void k_fused(
    const __nv_bfloat16* __restrict__ Axh, const __nv_bfloat16* __restrict__ Axl,
    const float* __restrict__ feat,
    const __nv_bfloat16* __restrict__ Wh, const __nv_bfloat16* __restrict__ Wl,
    float* __restrict__ lout,
    const float* __restrict__ conv_b, const float* __restrict__ proj_b,
    const float* __restrict__ skip_b, int M)
{
    extern __shared__ char sm[];
    uint32_t smb = smem_u32(sm);
    const uint32_t uAh = smb + SM_TILE;
    const uint32_t uAl = uAh + TILE_BYTES;
    const uint32_t uBh = uAl + TILE_BYTES;
    const uint32_t uBl = uBh + TILE_BYTES;
    float* sBiasC = (float*)(sm + SM_BIASC);
    float* sBiasO = (float*)(sm + SM_BIASO);

    int t = threadIdx.x, lane = t & 31, wid = t >> 5;
    int bm = blockIdx.y * 128;

    if (t < 128) {
        sBiasC[t] = conv_b[t];
        sBiasO[t] = proj_b[t] + skip_b[t];
    }

    int wm = (wid >> 2) * 64, wn = (wid & 3) * 32;
    const uint32_t aOff = (uint32_t)((wm + (lane & 7) + (lane & 8)) * TILE_STRIDE + ((lane & 16) ? 16 : 0));
    const uint32_t bOff = (uint32_t)((wn + (lane & 7) + ((lane & 16) ? 8 : 0)) * TILE_STRIDE + ((lane & 8) ? 16 : 0));

    float c[4][4][4];
#pragma unroll
    for (int i = 0; i < 4; i++)
#pragma unroll
        for (int j = 0; j < 4; j++)
#pragma unroll
            for (int k = 0; k < 4; k++) c[i][j][k] = 0.f;

    // ======== phase 1: conv = aggx @ Wc  (chunks 0..3) ========
#pragma unroll 1
    for (int ch = 0; ch < 4; ch++) {
        if (ch > 0) __syncthreads();
        // A: pre-split bf16 pair copy (ldab = 512)
#pragma unroll
        for (int i = 0; i < 8; i++) {
            int idx = t + i * 256;
            int r = idx >> 4, kc = idx & 15;
            int m = bm + r;
            uint4 vh, vl;
            if (m < M) {
                vh = *(const uint4*)(Axh + (size_t)m * HD + ch * 128 + kc * 8);
                vl = *(const uint4*)(Axl + (size_t)m * HD + ch * 128 + kc * 8);
            } else {
                vh = make_uint4(0, 0, 0, 0); vl = vh;
            }
            uint32_t off = (uint32_t)(r * TILE_STRIDE + kc * 16);
            *(uint4*)(sm + SM_TILE + off) = vh;
            *(uint4*)(sm + SM_TILE + TILE_BYTES + off) = vl;
        }
        // B: weight pair copy
#pragma unroll
        for (int i = 0; i < 8; i++) {
            int idx = t + i * 256;
            int r = idx >> 4, kc = idx & 15;
            uint4 vh = *(const uint4*)(Wh + (size_t)ch * 16384 + r * 128 + kc * 8);
            uint4 vl = *(const uint4*)(Wl + (size_t)ch * 16384 + r * 128 + kc * 8);
            uint32_t off = (uint32_t)(r * TILE_STRIDE + kc * 16);
            *(uint4*)(sm + SM_TILE + 2 * TILE_BYTES + off) = vh;
            *(uint4*)(sm + SM_TILE + 3 * TILE_BYTES + off) = vl;
        }
        __syncthreads();
#pragma unroll
        for (int pass = 0; pass < 3; pass++) {
            uint32_t aBase = ((pass == 2) ? uAl : uAh) + aOff;
            uint32_t bBase = ((pass == 1) ? uBl : uBh) + bOff;
#pragma unroll
            for (int k0 = 0; k0 < 8; k0++) {
                uint32_t ka = aBase + k0 * 32;
                uint32_t kb = bBase + k0 * 32;
                uint32_t a[4][4], b[4][2];
#pragma unroll
                for (int mt = 0; mt < 4; mt++)
                    LDM_X4(a[mt][0], a[mt][1], a[mt][2], a[mt][3], ka + mt * 16 * TILE_STRIDE);
#pragma unroll
                for (int np = 0; np < 2; np++)
                    LDM_X4(b[2 * np][0], b[2 * np][1], b[2 * np + 1][0], b[2 * np + 1][1],
                           kb + np * 16 * TILE_STRIDE);
#pragma unroll
                for (int mt = 0; mt < 4; mt++)
#pragma unroll
                    for (int nt = 0; nt < 4; nt++)
                        MMA_BF16(c[mt][nt], a[mt], b[nt]);
            }
        }
    }
    __syncthreads();   // all conv MMA done; smem tiles free

    // ======== conv epilogue in registers -> smem A tile (relu + bf16 split); reset acc ========
    {
        int g = lane >> 2, t2 = (lane & 3) * 2;
#pragma unroll
        for (int mt = 0; mt < 4; mt++) {
            int r0 = wm + mt * 16 + g;
#pragma unroll
            for (int nt = 0; nt < 4; nt++) {
                int col = wn + nt * 8 + t2;
                float bb0 = sBiasC[col], bb1 = sBiasC[col + 1];
                float o00 = fmaxf(c[mt][nt][0] + bb0, 0.f);
                float o01 = fmaxf(c[mt][nt][1] + bb1, 0.f);
                float o10 = fmaxf(c[mt][nt][2] + bb0, 0.f);
                float o11 = fmaxf(c[mt][nt][3] + bb1, 0.f);
                __nv_bfloat16 h00 = __float2bfloat16(o00), h01 = __float2bfloat16(o01);
                __nv_bfloat16 h10 = __float2bfloat16(o10), h11 = __float2bfloat16(o11);
                __nv_bfloat16 l00 = __float2bfloat16(o00 - __bfloat162float(h00));
                __nv_bfloat16 l01 = __float2bfloat16(o01 - __bfloat162float(h01));
                __nv_bfloat16 l10 = __float2bfloat16(o10 - __bfloat162float(h10));
                __nv_bfloat16 l11 = __float2bfloat16(o11 - __bfloat162float(h11));
                uint32_t offA = (uint32_t)(r0 * TILE_STRIDE + col * 2);
                uint32_t offB = (uint32_t)((r0 + 8) * TILE_STRIDE + col * 2);
                *(uint32_t*)(sm + SM_TILE + offA) = pack_bf2(h00, h01);
                *(uint32_t*)(sm + SM_TILE + TILE_BYTES + offA) = pack_bf2(l00, l01);
                *(uint32_t*)(sm + SM_TILE + offB) = pack_bf2(h10, h11);
                *(uint32_t*)(sm + SM_TILE + TILE_BYTES + offB) = pack_bf2(l10, l11);
                c[mt][nt][0] = 0.f; c[mt][nt][1] = 0.f;
                c[mt][nt][2] = 0.f; c[mt][nt][3] = 0.f;
            }
        }
    }
    // stage B (proj) while A writes settle
#pragma unroll
    for (int i = 0; i < 8; i++) {
        int idx = t + i * 256;
        int r = idx >> 4, kc = idx & 15;
        uint4 vh = *(const uint4*)(Wh + (size_t)4 * 16384 + r * 128 + kc * 8);
        uint4 vl = *(const uint4*)(Wl + (size_t)4 * 16384 + r * 128 + kc * 8);
        uint32_t off = (uint32_t)(r * TILE_STRIDE + kc * 16);
        *(uint4*)(sm + SM_TILE + 2 * TILE_BYTES + off) = vh;
        *(uint4*)(sm + SM_TILE + 3 * TILE_BYTES + off) = vl;
    }
    __syncthreads();

    // ======== phase 2: proj = relu(conv) @ Wp ========
#pragma unroll
    for (int pass = 0; pass < 3; pass++) {
        uint32_t aBase = ((pass == 2) ? uAl : uAh) + aOff;
        uint32_t bBase = ((pass == 1) ? uBl : uBh) + bOff;
#pragma unroll
        for (int k0 = 0; k0 < 8; k0++) {
            uint32_t ka = aBase + k0 * 32;
            uint32_t kb = bBase + k0 * 32;
            uint32_t a[4][4], b[4][2];
#pragma unroll
            for (int mt = 0; mt < 4; mt++)
                LDM_X4(a[mt][0], a[mt][1], a[mt][2], a[mt][3], ka + mt * 16 * TILE_STRIDE);
#pragma unroll
            for (int np = 0; np < 2; np++)
                LDM_X4(b[2 * np][0], b[2 * np][1], b[2 * np + 1][0], b[2 * np + 1][1],
                       kb + np * 16 * TILE_STRIDE);
#pragma unroll
            for (int mt = 0; mt < 4; mt++)
#pragma unroll
                for (int nt = 0; nt < 4; nt++)
                    MMA_BF16(c[mt][nt], a[mt], b[nt]);
        }
    }
    __syncthreads();

    // ======== phase 3: skip = feat @ Ws (A: fp32 convert) ========
#pragma unroll
    for (int i = 0; i < 8; i++) {
        int idx = t + i * 256;
        int r = idx >> 4, kc = idx & 15;
        int m = bm + r;
        float4 v0, v1;
        if (m < M) {
            const float4* p = (const float4*)(feat + (size_t)m * HID + kc * 8);
            v0 = p[0]; v1 = p[1];
        } else {
            v0 = make_float4(0.f, 0.f, 0.f, 0.f); v1 = v0;
        }
        float f[8] = {v0.x, v0.y, v0.z, v0.w, v1.x, v1.y, v1.z, v1.w};
        uint4 uh, ul;
        uint32_t* ph = (uint32_t*)&uh;
        uint32_t* pl = (uint32_t*)&ul;
#pragma unroll
        for (int j = 0; j < 4; j++) {
            float a = f[2 * j], b2 = f[2 * j + 1];
            __nv_bfloat16 ha = __float2bfloat16(a), hb = __float2bfloat16(b2);
            __nv_bfloat16 la = __float2bfloat16(a - __bfloat162float(ha));
            __nv_bfloat16 lb = __float2bfloat16(b2 - __bfloat162float(hb));
            ph[j] = pack_bf2(ha, hb);
            pl[j] = pack_bf2(la, lb);
        }
        uint32_t off = (uint32_t)(r * TILE_STRIDE + kc * 16);
        *(uint4*)(sm + SM_TILE + off) = uh;
        *(uint4*)(sm + SM_TILE + TILE_BYTES + off) = ul;
    }
#pragma unroll
    for (int i = 0; i < 8; i++) {
        int idx = t + i * 256;
        int r = idx >> 4, kc = idx & 15;
        uint4 vh = *(const uint4*)(Wh + (size_t)5 * 16384 + r * 128 + kc * 8);
        uint4 vl = *(const uint4*)(Wl + (size_t)5 * 16384 + r * 128 + kc * 8);
        uint32_t off = (uint32_t)(r * TILE_STRIDE + kc * 16);
        *(uint4*)(sm + SM_TILE + 2 * TILE_BYTES + off) = vh;
        *(uint4*)(sm + SM_TILE + 3 * TILE_BYTES + off) = vl;
    }
    __syncthreads();
#pragma unroll
    for (int pass = 0; pass < 3; pass++) {
        uint32_t aBase = ((pass == 2) ? uAl : uAh) + aOff;
        uint32_t bBase = ((pass == 1) ? uBl : uBh) + bOff;
#pragma unroll
        for (int k0 = 0; k0 < 8; k0++) {
            uint32_t ka = aBase + k0 * 32;
            uint32_t kb = bBase + k0 * 32;
            uint32_t a[4][4], b[4][2];
#pragma unroll
            for (int mt = 0; mt < 4; mt++)
                LDM_X4(a[mt][0], a[mt][1], a[mt][2], a[mt][3], ka + mt * 16 * TILE_STRIDE);
#pragma unroll
            for (int np = 0; np < 2; np++)
                LDM_X4(b[2 * np][0], b[2 * np][1], b[2 * np + 1][0], b[2 * np + 1][1],
                       kb + np * 16 * TILE_STRIDE);
#pragma unroll
            for (int mt = 0; mt < 4; mt++)
#pragma unroll
                for (int nt = 0; nt < 4; nt++)
                    MMA_BF16(c[mt][nt], a[mt], b[nt]);
        }
    }

    // ======== final epilogue: fp32 out ========
    {
        int g = lane >> 2, t2 = (lane & 3) * 2;
#pragma unroll
        for (int mt = 0; mt < 4; mt++) {
            int r0 = wm + mt * 16 + g;
            int m0 = bm + r0, m1 = m0 + 8;
#pragma unroll
            for (int nt = 0; nt < 4; nt++) {
                int col = wn + nt * 8 + t2;
                float bb0 = sBiasO[col], bb1 = sBiasO[col + 1];
                if (m0 < M) {
                    float2 o = {c[mt][nt][0] + bb0, c[mt][nt][1] + bb1};
                    *(float2*)(lout + (size_t)m0 * HID + col) = o;
                }
                if (m1 < M) {
                    float2 o = {c[mt][nt][2] + bb0, c[mt][nt][3] + bb1};
                    *(float2*)(lout + (size_t)m1 * HID + col) = o;
                }
            }
        }
    }
}

// ---------------- host orchestration ----------------
extern "C" void kernel_launch(void* const* d_in, const int* in_sizes, int n_in,
                              void* d_out, int out_size) {
    const float* x       = (const float*)d_in[0];
    const void*  ei      = d_in[1];
    const float* conv_w  = (const float*)d_in[2];
    const float* att_src = (const float*)d_in[3];
    const float* att_dst = (const float*)d_in[4];
    const float* conv_b  = (const float*)d_in[5];
    const float* proj_w  = (const float*)d_in[6];
    const float* proj_b  = (const float*)d_in[7];
    const float* skip_w  = (const float*)d_in[8];
    const float* skip_b  = (const float*)d_in[9];
    float* out = (float*)d_out;

    float *p_tmp, *p_va;
    __nv_bfloat16 *p_wth, *p_wtl, *p_axh, *p_axl;
    cudaGetSymbolAddress((void**)&p_tmp, g_tmp);
    cudaGetSymbolAddress((void**)&p_va, g_va);
    cudaGetSymbolAddress((void**)&p_wth, g_wth);
    cudaGetSymbolAddress((void**)&p_wtl, g_wtl);
    cudaGetSymbolAddress((void**)&p_axh, g_axh);
    cudaGetSymbolAddress((void**)&p_axl, g_axl);

    cudaFuncSetAttribute(k_fused, cudaFuncAttributeMaxDynamicSharedMemorySize, SM_TOT);

    // CSR build + weight prep (once per call)
    k_init<<<NBLK + 1, 256>>>((const unsigned int*)ei);
    k_degree<<<(NE + 255) / 256, 256>>>(ei);
    k_scan1<<<NBLK, 256>>>();
    k_scan2<<<1, 256>>>();
    k_scan3<<<NBLK, 256>>>();
    k_bucket<<<(NE + 255) / 256, 256>>>(ei);
    k_wprep<<<776, 256>>>(conv_w, proj_w, skip_w, att_src, att_dst);

    const float* feat = x;
    const int NWB = (NN + 7) / 8;     // warp-per-node blocks at 256 threads
    const int MT = (NN + 127) / 128;  // 391 M-tiles
    for (int l = 0; l < 2; l++) {
        float* lout = (l == 0) ? p_tmp : out;
        const __nv_bfloat16* wh = p_wth + (size_t)l * 98304;
        const __nv_bfloat16* wl = p_wtl + (size_t)l * 98304;
        k_alpha_x<<<NWB, 256>>>(feat, p_va + l * 1024);
        k_edge<<<NWB, 256>>>(feat);
        dim3 gc(1, MT);
        k_fused<<<gc, 256, SM_TOT>>>(p_axh, p_axl, feat, wh, wl, lout,
                                     conv_b + l * HID, proj_b + l * HID,
                                     skip_b + l * HID, NN);
        feat = p_tmp;
    }
}